// round 1
// baseline (speedup 1.0000x reference)
#include <cuda_runtime.h>

#define NG     512
#define W_IMG  256
#define H_IMG  256
#define NPIX   (W_IMG * H_IMG)
#define NEG_HALF_LOG2E (-0.7213475204444817f)   // -0.5 * log2(e)

__device__ __forceinline__ float ex2_approx(float x) {
    float y;
    asm("ex2.approx.f32 %0, %1;" : "=f"(y) : "f"(x));
    return y;
}
__device__ __forceinline__ float lg2_approx(float x) {
    float y;
    asm("lg2.approx.f32 %0, %1;" : "=f"(y) : "f"(x));
    return y;
}

__global__ __launch_bounds__(256) void Render_75617194213733_kernel(
    const float* __restrict__ means,    // [NG,2]
    const float* __restrict__ cov,      // [NG,2,2]
    const float* __restrict__ opac,     // [NG]
    const float* __restrict__ colors,   // [NG,3]
    float* __restrict__ out)            // [H,W,3]
{
    // Packed per-gaussian tables (broadcast LDS in the hot loop).
    __shared__ float4 S0[NG];  // mx, my, ka, kb
    __shared__ float4 S1[NG];  // kd, lop, cr, cg
    __shared__ float  S2[NG];  // cb

    const int tid = threadIdx.x;

    // Per-block prologue: pack 512 gaussians (2 per thread). Redundant across
    // blocks but trivial (~1% of work) and avoids global scratch.
    for (int g = tid; g < NG; g += 256) {
        float a = cov[g * 4 + 0];
        float b = cov[g * 4 + 1];
        float c = cov[g * 4 + 2];
        float d = cov[g * 4 + 3];
        float det = a * d - b * c;
        float s   = NEG_HALF_LOG2E / det;
        // mahalanobis = (d*dx^2 - (b+c)*dx*dy + a*dy^2) / det
        float ka = s * d;
        float kb = -s * (b + c);
        float kd = s * a;
        float lop = lg2_approx(opac[g]);   // fold opacity into the exponent
        S0[g] = make_float4(means[g * 2 + 0], means[g * 2 + 1], ka, kb);
        S1[g] = make_float4(kd, lop, colors[g * 3 + 0], colors[g * 3 + 1]);
        S2[g] = colors[g * 3 + 2];
    }
    __syncthreads();

    const int idx = blockIdx.x * 256 + tid;
    const float px = (float)(idx & (W_IMG - 1)) + 0.5f;
    const float py = (float)(idx >> 8) + 0.5f;

    float T = 1.0f;
    float r = 0.0f, gc = 0.0f, bc = 0.0f;

#pragma unroll 8
    for (int g = 0; g < NG; g++) {
        float4 p0 = S0[g];
        float4 p1 = S1[g];
        float dx = px - p0.x;
        float dy = py - p0.y;
        // m = ka*dx^2 + kb*dx*dy + kd*dy^2 + log2(op)   (all folded to base-2)
        float m = fmaf(dx, fmaf(p0.w, dy, p0.z * dx),
                       fmaf(p1.x * dy, dy, p1.y));
        float alpha = ex2_approx(m);            // = op * exp(-0.5*mahalanobis)
        float w = alpha * T;
        r  = fmaf(w, p1.z, r);
        gc = fmaf(w, p1.w, gc);
        bc = fmaf(w, S2[g], bc);
        float t = (1.0f - alpha) + 1e-7f;       // match reference op order
        T *= t;
    }

    out[idx * 3 + 0] = r;
    out[idx * 3 + 1] = gc;
    out[idx * 3 + 2] = bc;
}

extern "C" void kernel_launch(void* const* d_in, const int* in_sizes, int n_in,
                              void* d_out, int out_size) {
    const float* means  = nullptr;
    const float* cov    = nullptr;
    const float* opac   = nullptr;
    const float* colors = nullptr;
    for (int i = 0; i < n_in; i++) {
        switch (in_sizes[i]) {
            case NG * 2: means  = (const float*)d_in[i]; break;
            case NG * 4: cov    = (const float*)d_in[i]; break;
            case NG:     opac   = (const float*)d_in[i]; break;
            case NG * 3: colors = (const float*)d_in[i]; break;
            default: break;  // H/W scalars, if passed
        }
    }
    Render_75617194213733_kernel<<<NPIX / 256, 256>>>(means, cov, opac, colors,
                                                      (float*)d_out);
}

// round 2
// speedup vs baseline: 1.1330x; 1.1330x over previous
#include <cuda_runtime.h>

#define NG     512
#define W_IMG  256
#define H_IMG  256
#define NEG_HALF_LOG2E (-0.7213475204444817f)   // -0.5 * log2(e)

__device__ __forceinline__ float ex2_approx(float x) {
    float y;
    asm("ex2.approx.f32 %0, %1;" : "=f"(y) : "f"(x));
    return y;
}
__device__ __forceinline__ float lg2_approx(float x) {
    float y;
    asm("lg2.approx.f32 %0, %1;" : "=f"(y) : "f"(x));
    return y;
}
__device__ __forceinline__ float rcp_approx(float x) {
    float y;
    asm("rcp.approx.f32 %0, %1;" : "=f"(y) : "f"(x));
    return y;
}

__global__ __launch_bounds__(128) void Render_75617194213733_kernel(
    const float* __restrict__ means,    // [NG,2]
    const float* __restrict__ cov,      // [NG,2,2]
    const float* __restrict__ opac,     // [NG]
    const float* __restrict__ colors,   // [NG,3]
    float* __restrict__ out)            // [H,W,3]
{
    // Packed per-gaussian tables (broadcast LDS in the hot loop).
    __shared__ float4 S0[NG];  // mx, my, ka, kb
    __shared__ float4 S1[NG];  // kd, lop, cr, cg
    __shared__ float  S2[NG];  // cb

    const int tid = threadIdx.x;

    // Prologue: 4 gaussians per thread, approx-rcp instead of fp32 divide.
    for (int g = tid; g < NG; g += 128) {
        float a = cov[g * 4 + 0];
        float b = cov[g * 4 + 1];
        float c = cov[g * 4 + 2];
        float d = cov[g * 4 + 3];
        float det = fmaf(a, d, -b * c);
        float s   = NEG_HALF_LOG2E * rcp_approx(det);
        float ka = s * d;
        float kb = -s * (b + c);
        float kd = s * a;
        float lop = lg2_approx(opac[g]);   // fold opacity into the exponent
        S0[g] = make_float4(means[g * 2 + 0], means[g * 2 + 1], ka, kb);
        S1[g] = make_float4(kd, lop, colors[g * 3 + 0], colors[g * 3 + 1]);
        S2[g] = colors[g * 3 + 2];
    }
    __syncthreads();

    // One row per block; each thread handles two adjacent pixels (2*tid, 2*tid+1).
    const float px = (float)(2 * tid) + 0.5f;
    const float py = (float)blockIdx.x + 0.5f;

    float T1 = 1.0f, T2 = 1.0f;
    float r1 = 0.f, g1 = 0.f, b1 = 0.f;
    float r2 = 0.f, g2 = 0.f, b2 = 0.f;

#pragma unroll 8
    for (int g = 0; g < NG; g++) {
        float4 p0 = S0[g];                 // mx, my, ka, kb
        float4 p1 = S1[g];                 // kd, lop, cr, cg
        float cb = S2[g];
        float dx = px - p0.x;
        float dy = py - p0.y;
        float t1 = p0.z * dx;                              // ka*dx
        float t2 = fmaf(p0.w, dy, t1);                     // ka*dx + kb*dy
        float m1 = fmaf(dx, t2, fmaf(p1.x * dy, dy, p1.y)); // quad form + log2(op)
        // m(dx+1) = m(dx) + t2 + ka*dx + ka
        float m2 = (m1 + t2) + fmaf(p0.z, dx, p0.z);

        float a1 = ex2_approx(m1);
        float a2 = ex2_approx(m2);

        float w1 = a1 * T1;
        float w2 = a2 * T2;
        r1 = fmaf(w1, p1.z, r1);
        g1 = fmaf(w1, p1.w, g1);
        b1 = fmaf(w1, cb,   b1);
        r2 = fmaf(w2, p1.z, r2);
        g2 = fmaf(w2, p1.w, g2);
        b2 = fmaf(w2, cb,   b2);
        // T' = T*(1 - a + 1e-7) = fma(1e-7, T, T - w)
        T1 = fmaf(1e-7f, T1, T1 - w1);
        T2 = fmaf(1e-7f, T2, T2 - w2);
    }

    const int base = (blockIdx.x * W_IMG + 2 * tid) * 3;   // 6 floats, 8B-aligned
    float2* o2 = (float2*)(out + base);
    o2[0] = make_float2(r1, g1);
    o2[1] = make_float2(b1, r2);
    o2[2] = make_float2(g2, b2);
}

extern "C" void kernel_launch(void* const* d_in, const int* in_sizes, int n_in,
                              void* d_out, int out_size) {
    const float* means  = nullptr;
    const float* cov    = nullptr;
    const float* opac   = nullptr;
    const float* colors = nullptr;
    for (int i = 0; i < n_in; i++) {
        switch (in_sizes[i]) {
            case NG * 2: means  = (const float*)d_in[i]; break;
            case NG * 4: cov    = (const float*)d_in[i]; break;
            case NG:     opac   = (const float*)d_in[i]; break;
            case NG * 3: colors = (const float*)d_in[i]; break;
            default: break;  // H/W scalars, if passed
        }
    }
    Render_75617194213733_kernel<<<H_IMG, 128>>>(means, cov, opac, colors,
                                                 (float*)d_out);
}

// round 3
// speedup vs baseline: 2.2441x; 1.9806x over previous
#include <cuda_runtime.h>

#define NG      512
#define W_IMG   256
#define H_IMG   256
#define NEG_HALF_LOG2E (-0.7213475204444817f)   // -0.5 * log2(e)
#define LOG2EPS (-27.0f)                        // skip if max alpha < 2^-27

__device__ __forceinline__ float ex2_approx(float x) {
    float y; asm("ex2.approx.f32 %0, %1;" : "=f"(y) : "f"(x)); return y;
}
__device__ __forceinline__ float lg2_approx(float x) {
    float y; asm("lg2.approx.f32 %0, %1;" : "=f"(y) : "f"(x)); return y;
}
__device__ __forceinline__ float rcp_approx(float x) {
    float y; asm("rcp.approx.f32 %0, %1;" : "=f"(y) : "f"(x)); return y;
}

// Precomputed per-gaussian tables (built once by prep kernel).
__device__ float4 gP0[NG];   // mx, my, ka, kb
__device__ float4 gP1[NG];   // kd, lop, cr, cg
__device__ float  gP2[NG];   // cb
__device__ float2 gCull[NG]; // my, dymax2

__global__ __launch_bounds__(128) void prep_kernel(
    const float* __restrict__ means,
    const float* __restrict__ cov,
    const float* __restrict__ opac,
    const float* __restrict__ colors)
{
    for (int g = threadIdx.x; g < NG; g += 128) {
        float a = cov[g * 4 + 0];
        float b = cov[g * 4 + 1];
        float c = cov[g * 4 + 2];
        float d = cov[g * 4 + 3];
        float det = fmaf(a, d, -b * c);
        float s   = NEG_HALF_LOG2E * rcp_approx(det);
        float ka = s * d;           // < 0
        float kb = -s * (b + c);
        float kd = s * a;           // < 0
        float lop = lg2_approx(opac[g]);
        // max_x of (ka x^2 + kb x y + kd y^2) given y:  q*y^2,  q = kd - kb^2/(4 ka) < 0
        float q = kd - kb * kb * rcp_approx(4.0f * ka);
        // keep row iff q*dy^2 + lop > LOG2EPS  <=>  dy^2 < (LOG2EPS - lop)/q
        float dymax2 = (LOG2EPS - lop) * rcp_approx(q);
        gP0[g] = make_float4(means[g * 2 + 0], means[g * 2 + 1], ka, kb);
        gP1[g] = make_float4(kd, lop, colors[g * 3 + 0], colors[g * 3 + 1]);
        gP2[g] = colors[g * 3 + 2];
        gCull[g] = make_float2(means[g * 2 + 1], dymax2);
    }
}

__global__ __launch_bounds__(128) void Render_75617194213733_kernel(
    float* __restrict__ out)
{
    __shared__ float4 S0[NG];
    __shared__ float4 S1[NG];
    __shared__ float  S2[NG];
    __shared__ short  sIdx[NG];
    __shared__ int    sM;

    const int tid  = threadIdx.x;
    const float py = (float)blockIdx.x + 0.5f;

    // ── Row-level cull: warp 0 ballot-compacts surviving gaussian indices
    //    (order preserved: chunks in order, lanes in order within chunk).
    if (tid < 32) {
        int base = 0;
        const int lane = tid;
        const unsigned lanemask = (1u << lane) - 1u;
#pragma unroll
        for (int c = 0; c < NG / 32; c++) {
            int g = c * 32 + lane;
            float2 ci = gCull[g];
            float dy = py - ci.x;
            bool keep = (dy * dy < ci.y);
            unsigned ball = __ballot_sync(0xffffffffu, keep);
            if (keep) sIdx[base + __popc(ball & lanemask)] = (short)g;
            base += __popc(ball);
        }
        if (lane == 0) sM = base;
    }
    __syncthreads();

    const int M = sM;

    // ── Cooperative gather of survivors into packed shared arrays.
    for (int j = tid; j < M; j += 128) {
        int g = sIdx[j];
        S0[j] = gP0[g];
        S1[j] = gP1[g];
        S2[j] = gP2[g];
    }
    __syncthreads();

    // ── Hot loop: 2 adjacent pixels per thread over M survivors.
    const float px = (float)(2 * tid) + 0.5f;

    float T1 = 1.0f, T2 = 1.0f;
    float r1 = 0.f, g1 = 0.f, b1 = 0.f;
    float r2 = 0.f, g2 = 0.f, b2 = 0.f;

#pragma unroll 4
    for (int j = 0; j < M; j++) {
        float4 p0 = S0[j];                  // mx, my, ka, kb
        float4 p1 = S1[j];                  // kd, lop, cr, cg
        float cb = S2[j];
        float dx = px - p0.x;
        float dy = py - p0.y;
        float t1 = p0.z * dx;                               // ka*dx
        float t2 = fmaf(p0.w, dy, t1);                      // ka*dx + kb*dy
        float m1 = fmaf(dx, t2, fmaf(p1.x * dy, dy, p1.y)); // quad + log2(op)
        float m2 = (m1 + t2) + fmaf(p0.z, dx, p0.z);        // m(dx+1)

        float a1 = ex2_approx(m1);
        float a2 = ex2_approx(m2);

        float w1 = a1 * T1;
        float w2 = a2 * T2;
        r1 = fmaf(w1, p1.z, r1);
        g1 = fmaf(w1, p1.w, g1);
        b1 = fmaf(w1, cb,   b1);
        r2 = fmaf(w2, p1.z, r2);
        g2 = fmaf(w2, p1.w, g2);
        b2 = fmaf(w2, cb,   b2);
        T1 = fmaf(1e-7f, T1, T1 - w1);      // T *= (1 - a + 1e-7)
        T2 = fmaf(1e-7f, T2, T2 - w2);
    }

    const int base = (blockIdx.x * W_IMG + 2 * tid) * 3;
    float2* o2 = (float2*)(out + base);
    o2[0] = make_float2(r1, g1);
    o2[1] = make_float2(b1, r2);
    o2[2] = make_float2(g2, b2);
}

extern "C" void kernel_launch(void* const* d_in, const int* in_sizes, int n_in,
                              void* d_out, int out_size) {
    const float* means  = nullptr;
    const float* cov    = nullptr;
    const float* opac   = nullptr;
    const float* colors = nullptr;
    for (int i = 0; i < n_in; i++) {
        switch (in_sizes[i]) {
            case NG * 2: means  = (const float*)d_in[i]; break;
            case NG * 4: cov    = (const float*)d_in[i]; break;
            case NG:     opac   = (const float*)d_in[i]; break;
            case NG * 3: colors = (const float*)d_in[i]; break;
            default: break;
        }
    }
    prep_kernel<<<1, 128>>>(means, cov, opac, colors);
    Render_75617194213733_kernel<<<H_IMG, 128>>>((float*)d_out);
}

// round 4
// speedup vs baseline: 3.0203x; 1.3459x over previous
#include <cuda_runtime.h>

#define NG      512
#define W_IMG   256
#define H_IMG   256
#define NEG_HALF_LOG2E (-0.7213475204444817f)   // -0.5 * log2(e)
#define LOG2EPS (-27.0f)                        // skip if max alpha < 2^-27

__device__ __forceinline__ float ex2_approx(float x) {
    float y; asm("ex2.approx.f32 %0, %1;" : "=f"(y) : "f"(x)); return y;
}
__device__ __forceinline__ float lg2_approx(float x) {
    float y; asm("lg2.approx.f32 %0, %1;" : "=f"(y) : "f"(x)); return y;
}
__device__ __forceinline__ float rcp_approx(float x) {
    float y; asm("rcp.approx.f32 %0, %1;" : "=f"(y) : "f"(x)); return y;
}

// One block per row. 512 threads = 4 groups × 128; group g composites an
// ordered quarter of the surviving gaussians for pixel pair (2t, 2t+1);
// partial (color, transmittance) pairs are combined exactly at the end
// (compositing is an associative affine map).
__global__ __launch_bounds__(512) void Render_75617194213733_kernel(
    const float* __restrict__ means,    // [NG,2]
    const float* __restrict__ cov,      // [NG,2,2]
    const float* __restrict__ opac,     // [NG]
    const float* __restrict__ colors,   // [NG,3]
    float* __restrict__ out)            // [H,W,3]
{
    __shared__ float4 C0[NG];          // mx, my, ka, kb   (compacted)
    __shared__ float4 C1[NG];          // kd, lop, cr, cg
    __shared__ float  C2[NG];          // cb
    __shared__ float4 P1[3 * 128];     // partials for px1, groups 1..3
    __shared__ float4 P2[3 * 128];     // partials for px2, groups 1..3
    __shared__ int    sCnt[16];
    __shared__ int    sBase[16];
    __shared__ int    sM;

    const int tid  = threadIdx.x;
    const float py = (float)blockIdx.x + 0.5f;

    // ── Fused prep + row cull + direct compacted write (1 gaussian/thread).
    {
        const int g = tid;
        float4 cv = ((const float4*)cov)[g];          // a, b, c, d
        float2 mn = ((const float2*)means)[g];
        float  op = opac[g];
        float  cr = colors[3 * g + 0];
        float  cg = colors[3 * g + 1];
        float  cb = colors[3 * g + 2];

        float det = fmaf(cv.x, cv.w, -cv.y * cv.z);
        float s   = NEG_HALF_LOG2E * rcp_approx(det);
        float ka  = s * cv.w;                          // < 0
        float kb  = -s * (cv.y + cv.z);
        float kd  = s * cv.x;                          // < 0
        float lop = lg2_approx(op);
        // max over x of quad form given dy:  q*dy^2 + lop,  q = kd - kb^2/(4ka)
        float q   = kd - kb * kb * rcp_approx(4.0f * ka);
        float dy  = py - mn.y;
        bool keep = fmaf(q, dy * dy, lop) > LOG2EPS;

        const int lane = tid & 31;
        const int warp = tid >> 5;
        unsigned ball = __ballot_sync(0xffffffffu, keep);
        if (lane == 0) sCnt[warp] = __popc(ball);
        __syncthreads();
        if (tid == 0) {
            int b = 0;
#pragma unroll
            for (int w = 0; w < 16; w++) { sBase[w] = b; b += sCnt[w]; }
            sM = b;
        }
        __syncthreads();
        if (keep) {
            int j = sBase[warp] + __popc(ball & ((1u << lane) - 1u));
            C0[j] = make_float4(mn.x, mn.y, ka, kb);
            C1[j] = make_float4(kd, lop, cr, cg);
            C2[j] = cb;
        }
    }
    __syncthreads();

    const int M     = sM;
    const int Mq    = (M + 3) >> 2;
    const int group = tid >> 7;
    const int t     = tid & 127;
    const int j0    = min(group * Mq, M);
    const int j1    = min(j0 + Mq, M);

    const float px = (float)(2 * t) + 0.5f;

    float T1 = 1.0f, T2 = 1.0f;
    float r1 = 0.f, g1 = 0.f, b1 = 0.f;
    float r2 = 0.f, g2 = 0.f, b2 = 0.f;

#pragma unroll 4
    for (int j = j0; j < j1; j++) {
        float4 p0 = C0[j];                  // mx, my, ka, kb
        float4 p1 = C1[j];                  // kd, lop, cr, cg
        float cb = C2[j];
        float dx = px - p0.x;
        float dy = py - p0.y;
        float t1 = p0.z * dx;                               // ka*dx
        float t2 = fmaf(p0.w, dy, t1);                      // ka*dx + kb*dy
        float m1 = fmaf(dx, t2, fmaf(p1.x * dy, dy, p1.y)); // quad + log2(op)
        float m2 = (m1 + t2) + fmaf(p0.z, dx, p0.z);        // m(dx+1)

        float a1 = ex2_approx(m1);
        float a2 = ex2_approx(m2);

        float w1 = a1 * T1;
        float w2 = a2 * T2;
        r1 = fmaf(w1, p1.z, r1);
        g1 = fmaf(w1, p1.w, g1);
        b1 = fmaf(w1, cb,   b1);
        r2 = fmaf(w2, p1.z, r2);
        g2 = fmaf(w2, p1.w, g2);
        b2 = fmaf(w2, cb,   b2);
        T1 = fmaf(1e-7f, T1, T1 - w1);      // T *= (1 - a + 1e-7)
        T2 = fmaf(1e-7f, T2, T2 - w2);
    }

    // ── Exact segment combine: C = C_a + T_a * C_b (fold groups 3→2→1→0).
    if (group != 0) {
        int pi = (group - 1) * 128 + t;
        P1[pi] = make_float4(r1, g1, b1, T1);
        P2[pi] = make_float4(r2, g2, b2, T2);
    }
    __syncthreads();
    if (group == 0) {
        float4 q1 = P1[t], q2 = P1[128 + t], q3 = P1[256 + t];
        float rr = fmaf(q2.w, q3.x, q2.x);
        float gg = fmaf(q2.w, q3.y, q2.y);
        float bb = fmaf(q2.w, q3.z, q2.z);
        rr = fmaf(q1.w, rr, q1.x);
        gg = fmaf(q1.w, gg, q1.y);
        bb = fmaf(q1.w, bb, q1.z);
        float R1 = fmaf(T1, rr, r1);
        float G1 = fmaf(T1, gg, g1);
        float B1 = fmaf(T1, bb, b1);

        float4 u1 = P2[t], u2 = P2[128 + t], u3 = P2[256 + t];
        rr = fmaf(u2.w, u3.x, u2.x);
        gg = fmaf(u2.w, u3.y, u2.y);
        bb = fmaf(u2.w, u3.z, u2.z);
        rr = fmaf(u1.w, rr, u1.x);
        gg = fmaf(u1.w, gg, u1.y);
        bb = fmaf(u1.w, bb, u1.z);
        float R2 = fmaf(T2, rr, r2);
        float G2 = fmaf(T2, gg, g2);
        float B2 = fmaf(T2, bb, b2);

        const int base = (blockIdx.x * W_IMG + 2 * t) * 3;
        float2* o2 = (float2*)(out + base);
        o2[0] = make_float2(R1, G1);
        o2[1] = make_float2(B1, R2);
        o2[2] = make_float2(G2, B2);
    }
}

extern "C" void kernel_launch(void* const* d_in, const int* in_sizes, int n_in,
                              void* d_out, int out_size) {
    const float* means  = nullptr;
    const float* cov    = nullptr;
    const float* opac   = nullptr;
    const float* colors = nullptr;
    for (int i = 0; i < n_in; i++) {
        switch (in_sizes[i]) {
            case NG * 2: means  = (const float*)d_in[i]; break;
            case NG * 4: cov    = (const float*)d_in[i]; break;
            case NG:     opac   = (const float*)d_in[i]; break;
            case NG * 3: colors = (const float*)d_in[i]; break;
            default: break;
        }
    }
    Render_75617194213733_kernel<<<H_IMG, 512>>>(means, cov, opac, colors,
                                                 (float*)d_out);
}

// round 5
// speedup vs baseline: 3.0292x; 1.0029x over previous
#include <cuda_runtime.h>

#define NG      512
#define W_IMG   256
#define H_IMG   256
#define NEG_HALF_LOG2E (-0.7213475204444817f)   // -0.5 * log2(e)
#define LOG2EPS (-27.0f)                        // skip if max alpha < 2^-27

__device__ __forceinline__ float ex2_approx(float x) {
    float y; asm("ex2.approx.f32 %0, %1;" : "=f"(y) : "f"(x)); return y;
}
__device__ __forceinline__ float lg2_approx(float x) {
    float y; asm("lg2.approx.f32 %0, %1;" : "=f"(y) : "f"(x)); return y;
}
__device__ __forceinline__ float rcp_approx(float x) {
    float y; asm("rcp.approx.f32 %0, %1;" : "=f"(y) : "f"(x)); return y;
}

// One block per row. 512 threads = 4 groups × 128; group g composites an
// ordered quarter of the surviving gaussians for pixel pair (2t, 2t+1);
// partials combined exactly (compositing is an associative affine map).
// Row-uniform terms (kb*dy, kd*dy^2+log2(op)) are folded into the compacted
// record, so the hot loop is 2 LDS.128 + ~19 fma-class ops + 2 MUFU per
// gaussian per pixel-pair, with a 4-cycle serial chain through T.
__global__ __launch_bounds__(512) void Render_75617194213733_kernel(
    const float* __restrict__ means,    // [NG,2]
    const float* __restrict__ cov,      // [NG,2,2]
    const float* __restrict__ opac,     // [NG]
    const float* __restrict__ colors,   // [NG,3]
    float* __restrict__ out)            // [H,W,3]
{
    __shared__ float4 C0[NG];          // mx, ka, kb*dy, kd*dy^2+lop   (compacted)
    __shared__ float4 C1[NG];          // cr, cg, cb, -
    __shared__ float4 P1[3 * 128];     // partials px1, groups 1..3
    __shared__ float4 P2[3 * 128];     // partials px2, groups 1..3
    __shared__ int    sCnt[16];

    const int tid  = threadIdx.x;
    const int lane = tid & 31;
    const int warp = tid >> 5;
    const float py = (float)blockIdx.x + 0.5f;

    int M;
    // ── Fused prep + row cull + direct compacted write (1 gaussian/thread).
    {
        const int g = tid;
        float4 cv = ((const float4*)cov)[g];          // a, b, c, d
        float2 mn = ((const float2*)means)[g];
        float  op = opac[g];
        float  cr = colors[3 * g + 0];
        float  cg = colors[3 * g + 1];
        float  cb = colors[3 * g + 2];

        float det = fmaf(cv.x, cv.w, -cv.y * cv.z);
        float s   = NEG_HALF_LOG2E * rcp_approx(det);
        float ka  = s * cv.w;                          // < 0
        float kb  = -s * (cv.y + cv.z);
        float kd  = s * cv.x;                          // < 0
        float lop = lg2_approx(op);
        // max over x of quad form given dy:  q*dy^2 + lop,  q = kd - kb^2/(4ka)
        float q   = kd - kb * kb * rcp_approx(4.0f * ka);
        float dy  = py - mn.y;
        bool keep = fmaf(q, dy * dy, lop) > LOG2EPS;

        unsigned ball = __ballot_sync(0xffffffffu, keep);
        if (lane == 0) sCnt[warp] = __popc(ball);
        __syncthreads();
        int base = 0;
        M = 0;
#pragma unroll
        for (int w = 0; w < 16; w++) {
            int c = sCnt[w];
            if (w < warp) base += c;
            M += c;
        }
        if (keep) {
            int j = base + __popc(ball & ((1u << lane) - 1u));
            float kbdy = kb * dy;
            float c1   = fmaf(kd * dy, dy, lop);       // kd*dy^2 + log2(op)
            C0[j] = make_float4(mn.x, ka, kbdy, c1);
            C1[j] = make_float4(cr, cg, cb, 0.0f);
        }
    }
    __syncthreads();

    const int Mq    = (M + 3) >> 2;
    const int group = tid >> 7;
    const int t     = tid & 127;
    const int j0    = min(group * Mq, M);
    const int j1    = min(j0 + Mq, M);

    const float px = (float)(2 * t) + 0.5f;

    float T1 = 1.0f, T2 = 1.0f;
    float r1 = 0.f, g1 = 0.f, b1 = 0.f;
    float r2 = 0.f, g2 = 0.f, b2 = 0.f;

#pragma unroll 4
    for (int j = j0; j < j1; j++) {
        float4 p0 = C0[j];                  // mx, ka, kbdy, c1
        float4 p1 = C1[j];                  // cr, cg, cb, -
        float dx = px - p0.x;
        float t2 = fmaf(p0.y, dx, p0.z);                // ka*dx + kb*dy
        float m1 = fmaf(dx, t2, p0.w);                  // full folded exponent
        float m2 = (m1 + t2) + fmaf(p0.y, dx, p0.y);    // m(dx+1)

        float a1 = ex2_approx(m1);
        float a2 = ex2_approx(m2);

        float w1 = a1 * T1;
        float w2 = a2 * T2;
        float u1 = 1.0000001f - a1;         // (1 - a) + 1e-7, off the T-chain
        float u2 = 1.0000001f - a2;
        r1 = fmaf(w1, p1.x, r1);
        g1 = fmaf(w1, p1.y, g1);
        b1 = fmaf(w1, p1.z, b1);
        r2 = fmaf(w2, p1.x, r2);
        g2 = fmaf(w2, p1.y, g2);
        b2 = fmaf(w2, p1.z, b2);
        T1 *= u1;                           // 4-cycle serial chain
        T2 *= u2;
    }

    // ── Exact segment combine: C = C_a + T_a * C_b (fold groups 3→2→1→0).
    if (group != 0) {
        int pi = (group - 1) * 128 + t;
        P1[pi] = make_float4(r1, g1, b1, T1);
        P2[pi] = make_float4(r2, g2, b2, T2);
    }
    __syncthreads();
    if (group == 0) {
        float4 q1 = P1[t], q2 = P1[128 + t], q3 = P1[256 + t];
        float rr = fmaf(q2.w, q3.x, q2.x);
        float gg = fmaf(q2.w, q3.y, q2.y);
        float bb = fmaf(q2.w, q3.z, q2.z);
        rr = fmaf(q1.w, rr, q1.x);
        gg = fmaf(q1.w, gg, q1.y);
        bb = fmaf(q1.w, bb, q1.z);
        float R1 = fmaf(T1, rr, r1);
        float G1 = fmaf(T1, gg, g1);
        float B1 = fmaf(T1, bb, b1);

        float4 u1 = P2[t], u2 = P2[128 + t], u3 = P2[256 + t];
        rr = fmaf(u2.w, u3.x, u2.x);
        gg = fmaf(u2.w, u3.y, u2.y);
        bb = fmaf(u2.w, u3.z, u2.z);
        rr = fmaf(u1.w, rr, u1.x);
        gg = fmaf(u1.w, gg, u1.y);
        bb = fmaf(u1.w, bb, u1.z);
        float R2 = fmaf(T2, rr, r2);
        float G2 = fmaf(T2, gg, g2);
        float B2 = fmaf(T2, bb, b2);

        const int base = (blockIdx.x * W_IMG + 2 * t) * 3;
        float2* o2 = (float2*)(out + base);
        o2[0] = make_float2(R1, G1);
        o2[1] = make_float2(B1, R2);
        o2[2] = make_float2(G2, B2);
    }
}

extern "C" void kernel_launch(void* const* d_in, const int* in_sizes, int n_in,
                              void* d_out, int out_size) {
    const float* means  = nullptr;
    const float* cov    = nullptr;
    const float* opac   = nullptr;
    const float* colors = nullptr;
    for (int i = 0; i < n_in; i++) {
        switch (in_sizes[i]) {
            case NG * 2: means  = (const float*)d_in[i]; break;
            case NG * 4: cov    = (const float*)d_in[i]; break;
            case NG:     opac   = (const float*)d_in[i]; break;
            case NG * 3: colors = (const float*)d_in[i]; break;
            default: break;
        }
    }
    Render_75617194213733_kernel<<<H_IMG, 512>>>(means, cov, opac, colors,
                                                 (float*)d_out);
}

// round 6
// speedup vs baseline: 3.8339x; 1.2657x over previous
#include <cuda_runtime.h>

#define NG      512
#define W_IMG   256
#define H_IMG   256
#define NEG_HALF_LOG2E (-0.7213475204444817f)   // -0.5 * log2(e)
#define LOG2EPS (-27.0f)                        // skip if max alpha < 2^-27

__device__ __forceinline__ float ex2_approx(float x) {
    float y; asm("ex2.approx.f32 %0, %1;" : "=f"(y) : "f"(x)); return y;
}
__device__ __forceinline__ float lg2_approx(float x) {
    float y; asm("lg2.approx.f32 %0, %1;" : "=f"(y) : "f"(x)); return y;
}
__device__ __forceinline__ float rcp_approx(float x) {
    float y; asm("rcp.approx.f32 %0, %1;" : "=f"(y) : "f"(x)); return y;
}

// One block per row, 256 threads = 4 groups × 64; each thread composites an
// ordered quarter of the survivors for 4 adjacent pixels (second-difference
// update of the quadratic exponent). Partials combined exactly at the end.
__global__ __launch_bounds__(256) void Render_75617194213733_kernel(
    const float* __restrict__ means,    // [NG,2]
    const float* __restrict__ cov,      // [NG,2,2]
    const float* __restrict__ opac,     // [NG]
    const float* __restrict__ colors,   // [NG,3]
    float* __restrict__ out)            // [H,W,3]
{
    __shared__ float4 C[2 * NG];        // interleaved: [2j]=(mx,ka,kb*dy,kd*dy^2+lop)
                                        //              [2j+1]=(cr,cg,cb,2ka)
    __shared__ float4 Ppart[4][3 * 64]; // per-pixel partials, groups 1..3
    __shared__ int    sCnt[16];

    const int tid  = threadIdx.x;
    const int lane = tid & 31;
    const int warp = tid >> 5;
    const float py = (float)blockIdx.x + 0.5f;

    int M;
    // ── Fused prep + row cull + ordered compacted write (2 gaussians/thread).
    {
        float4 A[2];  // mx, ka, kbdy, c1
        float4 B[2];  // cr, cg, cb, 2ka
        bool   kp[2];
        unsigned bl[2];
#pragma unroll
        for (int c = 0; c < 2; c++) {
            const int g = tid + 256 * c;
            float4 cv = ((const float4*)cov)[g];
            float2 mn = ((const float2*)means)[g];
            float  op = opac[g];
            float det = fmaf(cv.x, cv.w, -cv.y * cv.z);
            float s   = NEG_HALF_LOG2E * rcp_approx(det);
            float ka  = s * cv.w;
            float kb  = -s * (cv.y + cv.z);
            float kd  = s * cv.x;
            float lop = lg2_approx(op);
            float q   = kd - kb * kb * rcp_approx(4.0f * ka);
            float dy  = py - mn.y;
            kp[c] = fmaf(q, dy * dy, lop) > LOG2EPS;
            bl[c] = __ballot_sync(0xffffffffu, kp[c]);
            if (lane == 0) sCnt[c * 8 + warp] = __popc(bl[c]);
            A[c] = make_float4(mn.x, ka, kb * dy, fmaf(kd * dy, dy, lop));
            B[c] = make_float4(colors[3 * g + 0], colors[3 * g + 1],
                               colors[3 * g + 2], ka + ka);
        }
        __syncthreads();
        int base0 = 0, base1 = 0;
        M = 0;
#pragma unroll
        for (int w = 0; w < 16; w++) {
            int cnt = sCnt[w];
            if (w < warp)     base0 += cnt;
            if (w < 8 + warp) base1 += cnt;
            M += cnt;
        }
        if (kp[0]) {
            int j = base0 + __popc(bl[0] & ((1u << lane) - 1u));
            C[2 * j]     = A[0];
            C[2 * j + 1] = B[0];
        }
        if (kp[1]) {
            int j = base1 + __popc(bl[1] & ((1u << lane) - 1u));
            C[2 * j]     = A[1];
            C[2 * j + 1] = B[1];
        }
    }
    __syncthreads();

    const int Mq    = (M + 3) >> 2;
    const int group = tid >> 6;
    const int t     = tid & 63;
    const int j0    = min(group * Mq, M);
    const int j1    = min(j0 + Mq, M);

    const float px = (float)(4 * t) + 0.5f;

    float T0 = 1.f, T1 = 1.f, T2 = 1.f, T3 = 1.f;
    float r0 = 0.f, g0 = 0.f, b0 = 0.f;
    float r1 = 0.f, g1 = 0.f, b1 = 0.f;
    float r2 = 0.f, g2 = 0.f, b2 = 0.f;
    float r3 = 0.f, g3 = 0.f, b3 = 0.f;

#pragma unroll 2
    for (int j = j0; j < j1; j++) {
        float4 pa = C[2 * j];           // mx, ka, kbdy, c1
        float4 pb = C[2 * j + 1];       // cr, cg, cb, 2ka
        float dx = px - pa.x;
        float t2 = fmaf(pa.y, dx, pa.z);          // ka*dx + kb*dy
        float m0 = fmaf(dx, t2, pa.w);            // folded exponent at px
        float s0 = t2 + fmaf(pa.y, dx, pa.y);     // ka*(2dx+1) + kb*dy
        float m1 = m0 + s0;
        float s1 = s0 + pb.w;
        float m2 = m1 + s1;
        float s2 = s1 + pb.w;
        float m3 = m2 + s2;

        float a0 = ex2_approx(m0);
        float a1 = ex2_approx(m1);
        float a2 = ex2_approx(m2);
        float a3 = ex2_approx(m3);

        float w0 = a0 * T0, w1 = a1 * T1, w2 = a2 * T2, w3 = a3 * T3;
        r0 = fmaf(w0, pb.x, r0); g0 = fmaf(w0, pb.y, g0); b0 = fmaf(w0, pb.z, b0);
        r1 = fmaf(w1, pb.x, r1); g1 = fmaf(w1, pb.y, g1); b1 = fmaf(w1, pb.z, b1);
        r2 = fmaf(w2, pb.x, r2); g2 = fmaf(w2, pb.y, g2); b2 = fmaf(w2, pb.z, b2);
        r3 = fmaf(w3, pb.x, r3); g3 = fmaf(w3, pb.y, g3); b3 = fmaf(w3, pb.z, b3);
        T0 *= 1.0000001f - a0;          // (1 - a) + 1e-7, off the critical chain
        T1 *= 1.0000001f - a1;
        T2 *= 1.0000001f - a2;
        T3 *= 1.0000001f - a3;
    }

    // ── Exact segment combine: C = C_a + T_a * C_b (fold groups 3→2→1→0).
    if (group != 0) {
        int pi = (group - 1) * 64 + t;
        Ppart[0][pi] = make_float4(r0, g0, b0, T0);
        Ppart[1][pi] = make_float4(r1, g1, b1, T1);
        Ppart[2][pi] = make_float4(r2, g2, b2, T2);
        Ppart[3][pi] = make_float4(r3, g3, b3, T3);
    }
    __syncthreads();
    if (group == 0) {
        float R[4], G[4], B[4];
        float rl[4] = {r0, r1, r2, r3};
        float gl[4] = {g0, g1, g2, g3};
        float bl_[4] = {b0, b1, b2, b3};
        float Tl[4] = {T0, T1, T2, T3};
#pragma unroll
        for (int p = 0; p < 4; p++) {
            float4 q1 = Ppart[p][t];
            float4 q2 = Ppart[p][64 + t];
            float4 q3 = Ppart[p][128 + t];
            float rr = fmaf(q2.w, q3.x, q2.x);
            float gg = fmaf(q2.w, q3.y, q2.y);
            float bb = fmaf(q2.w, q3.z, q2.z);
            rr = fmaf(q1.w, rr, q1.x);
            gg = fmaf(q1.w, gg, q1.y);
            bb = fmaf(q1.w, bb, q1.z);
            R[p] = fmaf(Tl[p], rr, rl[p]);
            G[p] = fmaf(Tl[p], gg, gl[p]);
            B[p] = fmaf(Tl[p], bb, bl_[p]);
        }
        // 4 px × RGB = 12 floats, 16B-aligned (48-byte stride per thread).
        float4* o4 = (float4*)(out + (blockIdx.x * W_IMG + 4 * t) * 3);
        o4[0] = make_float4(R[0], G[0], B[0], R[1]);
        o4[1] = make_float4(G[1], B[1], R[2], G[2]);
        o4[2] = make_float4(B[2], R[3], G[3], B[3]);
    }
}

extern "C" void kernel_launch(void* const* d_in, const int* in_sizes, int n_in,
                              void* d_out, int out_size) {
    const float* means  = nullptr;
    const float* cov    = nullptr;
    const float* opac   = nullptr;
    const float* colors = nullptr;
    for (int i = 0; i < n_in; i++) {
        switch (in_sizes[i]) {
            case NG * 2: means  = (const float*)d_in[i]; break;
            case NG * 4: cov    = (const float*)d_in[i]; break;
            case NG:     opac   = (const float*)d_in[i]; break;
            case NG * 3: colors = (const float*)d_in[i]; break;
            default: break;
        }
    }
    Render_75617194213733_kernel<<<H_IMG, 256>>>(means, cov, opac, colors,
                                                 (float*)d_out);
}